// round 2
// baseline (speedup 1.0000x reference)
#include <cuda_runtime.h>
#include <math.h>

#define M_ROWS 100352   // 32 * 3136 = 2048 windows * 49
#define CDIM   192
#define HIDDEN 768
#define QKV3   576

// ---------------- scratch (no allocs allowed) ----------------
__device__ float g_xw  [(size_t)M_ROWS * CDIM];    // LN1 + shifted window-partitioned input
__device__ float g_qkv [(size_t)M_ROWS * QKV3];    // qkv projections
__device__ float g_attn[(size_t)M_ROWS * CDIM];    // attention output (window layout)
__device__ float g_y   [(size_t)M_ROWS * CDIM];    // LN2 output
__device__ float g_h   [(size_t)M_ROWS * HIDDEN];  // fc1+gelu output

// window-layout row -> token index (handles cyclic shift by +3 on both axes)
__device__ __forceinline__ size_t win_row_to_token(int r) {
    int win = r / 49;
    int n   = r - win * 49;
    int b   = win >> 6;          // batch
    int wi  = win & 63;          // window within image (8x8)
    int ri  = n / 7;
    int ci  = n - ri * 7;
    int hs = (wi >> 3) * 7 + ri + 3; if (hs >= 56) hs -= 56;
    int ws = (wi & 7)  * 7 + ci + 3; if (ws >= 56) ws -= 56;
    return (size_t)b * 3136 + (size_t)hs * 56 + ws;
}

// ---------------- LayerNorm (1 warp per row) ----------------
template<bool GATHER>
__global__ __launch_bounds__(256)
void ln_kernel(const float* __restrict__ in, const float* __restrict__ gamma,
               const float* __restrict__ beta, float* __restrict__ out) {
    int row  = blockIdx.x * 8 + (threadIdx.x >> 5);
    int lane = threadIdx.x & 31;
    size_t t = GATHER ? win_row_to_token(row) : (size_t)row;
    const float* p = in + t * CDIM;
    float v[6];
    float s = 0.f, ss = 0.f;
#pragma unroll
    for (int i = 0; i < 6; i++) {
        v[i] = p[lane + 32 * i];
        s  += v[i];
        ss += v[i] * v[i];
    }
#pragma unroll
    for (int o = 16; o; o >>= 1) {
        s  += __shfl_xor_sync(0xffffffffu, s, o);
        ss += __shfl_xor_sync(0xffffffffu, ss, o);
    }
    float mu   = s * (1.f / CDIM);
    float var  = ss * (1.f / CDIM) - mu * mu;
    float rinv = rsqrtf(var + 1e-5f);
    float* q = out + (size_t)row * CDIM;
#pragma unroll
    for (int i = 0; i < 6; i++) {
        int c = lane + 32 * i;
        q[c] = (v[i] - mu) * rinv * gamma[c] + beta[c];
    }
}

// ---------------- tiled fp32 GEMM, fused epilogues ----------------
// MODE 0: C = A@B + bias                              (qkv)
// MODE 1: d_out[token] = x[token] + A@B + bias        (proj + window-reverse + residual)
// MODE 2: C = gelu(A@B + bias)                        (fc1)
// MODE 3: C += A@B + bias                             (fc2 + residual into d_out)
template<int MODE>
__global__ __launch_bounds__(256)
void gemm_kernel(const float* __restrict__ A, const float* __restrict__ Bw,
                 const float* __restrict__ bias, float* __restrict__ C,
                 const float* __restrict__ extra, int K, int N) {
    __shared__ float As[8][132];   // padded: conflict-free transposed store
    __shared__ float Bs[8][64];

    int tid  = threadIdx.x;
    int row0 = blockIdx.y * 128;
    int col0 = blockIdx.x * 64;
    int ty = tid >> 4;             // 0..15 -> 8 rows each
    int tx = tid & 15;             // 0..15 -> 4 cols each

    float acc[8][4];
#pragma unroll
    for (int i = 0; i < 8; i++)
#pragma unroll
        for (int j = 0; j < 4; j++) acc[i][j] = 0.f;

    int ar = tid >> 1;             // 0..127
    int ac = (tid & 1) * 4;        // 0 or 4
    int br = tid >> 4;             // 0..7   (only tid<128 loads B)
    int bc = (tid & 15) * 4;

    const float* Aptr = A + (size_t)(row0 + ar) * K + ac;

    for (int k0 = 0; k0 < K; k0 += 8) {
        float4 av = *(const float4*)(Aptr + k0);
        As[ac + 0][ar] = av.x;
        As[ac + 1][ar] = av.y;
        As[ac + 2][ar] = av.z;
        As[ac + 3][ar] = av.w;
        if (tid < 128) {
            float4 bv = *(const float4*)(Bw + (size_t)(k0 + br) * N + col0 + bc);
            *(float4*)&Bs[br][bc] = bv;
        }
        __syncthreads();
#pragma unroll
        for (int k = 0; k < 8; k++) {
            float a[8], b[4];
            *(float4*)(a)     = *(const float4*)&As[k][ty * 8];
            *(float4*)(a + 4) = *(const float4*)&As[k][ty * 8 + 4];
            *(float4*)(b)     = *(const float4*)&Bs[k][tx * 4];
#pragma unroll
            for (int i = 0; i < 8; i++)
#pragma unroll
                for (int j = 0; j < 4; j++)
                    acc[i][j] = fmaf(a[i], b[j], acc[i][j]);
        }
        __syncthreads();
    }

    int cbase = col0 + tx * 4;
    float4 bv = *(const float4*)(bias + cbase);
#pragma unroll
    for (int i = 0; i < 8; i++) {
        int r = row0 + ty * 8 + i;
        float4 o;
        o.x = acc[i][0] + bv.x;
        o.y = acc[i][1] + bv.y;
        o.z = acc[i][2] + bv.z;
        o.w = acc[i][3] + bv.w;
        if (MODE == 0) {
            *(float4*)(C + (size_t)r * N + cbase) = o;
        } else if (MODE == 1) {
            size_t t = win_row_to_token(r);
            float4 xv = *(const float4*)(extra + t * CDIM + cbase);
            o.x += xv.x; o.y += xv.y; o.z += xv.z; o.w += xv.w;
            *(float4*)(C + t * CDIM + cbase) = o;
        } else if (MODE == 2) {
            o.x = 0.5f * o.x * (1.f + erff(o.x * 0.70710678118654752f));
            o.y = 0.5f * o.y * (1.f + erff(o.y * 0.70710678118654752f));
            o.z = 0.5f * o.z * (1.f + erff(o.z * 0.70710678118654752f));
            o.w = 0.5f * o.w * (1.f + erff(o.w * 0.70710678118654752f));
            *(float4*)(C + (size_t)r * N + cbase) = o;
        } else {  // MODE 3
            float4 cv = *(const float4*)(C + (size_t)r * N + cbase);
            o.x += cv.x; o.y += cv.y; o.z += cv.z; o.w += cv.w;
            *(float4*)(C + (size_t)r * N + cbase) = o;
        }
    }
}

// ---------------- windowed attention: 1 block per (window, head) ----------------
__global__ __launch_bounds__(256)
void attn_kernel(const float* __restrict__ qkv, const float* __restrict__ rpb,
                 float* __restrict__ outp) {
    int blk  = blockIdx.x;
    int win  = blk / 6;
    int head = blk % 6;

    __shared__ float qs[49 * 32];    // [n][d]
    __shared__ float ksT[32 * 49];   // [d][n]  (transposed: conflict-free QK)
    __shared__ float vs[49 * 32];    // [n][d]
    __shared__ float sc[49 * 49];

    int tid = threadIdx.x;
    const float* base = qkv + (size_t)win * 49 * QKV3;

    for (int e = tid; e < 49 * 32; e += 256) {
        int n = e >> 5, d = e & 31;
        qs[e]            = base[n * QKV3 + head * 32 + d] * 0.17677669529663687f;
        ksT[d * 49 + n]  = base[n * QKV3 + 192 + head * 32 + d];
        vs[e]            = base[n * QKV3 + 384 + head * 32 + d];
    }
    __syncthreads();

    int wi = win & 63;
    int wy = wi >> 3, wx = wi & 7;

    for (int e = tid; e < 49 * 49; e += 256) {
        int i = e / 49, j = e - i * 49;
        const float* qi = qs + i * 32;
        float accv = 0.f;
#pragma unroll
        for (int d = 0; d < 32; d++)
            accv = fmaf(qi[d], ksT[d * 49 + j], accv);

        int yi = i / 7, xi = i - yi * 7;
        int yj = j / 7, xj = j - yj * 7;
        int idx = (yi - yj + 6) * 13 + (xi - xj + 6);
        accv += rpb[idx * 6 + head];

        // shift mask on shifted-image coordinates
        int ri = wy * 7 + yi, ci = wx * 7 + xi;
        int rj = wy * 7 + yj, cj = wx * 7 + xj;
        int gi = (ri < 49 ? 0 : (ri < 53 ? 1 : 2)) * 3 + (ci < 49 ? 0 : (ci < 53 ? 1 : 2));
        int gj = (rj < 49 ? 0 : (rj < 53 ? 1 : 2)) * 3 + (cj < 49 ? 0 : (cj < 53 ? 1 : 2));
        if (gi != gj) accv -= 100.f;
        sc[e] = accv;
    }
    __syncthreads();

    // softmax: 1 warp per row
    int warp = tid >> 5, lane = tid & 31;
    for (int i = warp; i < 49; i += 8) {
        float v0 = (lane < 49)      ? sc[i * 49 + lane]      : -1e30f;
        float v1 = (lane + 32 < 49) ? sc[i * 49 + lane + 32] : -1e30f;
        float m = fmaxf(v0, v1);
#pragma unroll
        for (int o = 16; o; o >>= 1) m = fmaxf(m, __shfl_xor_sync(0xffffffffu, m, o));
        float e0 = (lane < 49)      ? __expf(v0 - m) : 0.f;
        float e1 = (lane + 32 < 49) ? __expf(v1 - m) : 0.f;
        float s = e0 + e1;
#pragma unroll
        for (int o = 16; o; o >>= 1) s += __shfl_xor_sync(0xffffffffu, s, o);
        float inv = 1.f / s;
        if (lane < 49)      sc[i * 49 + lane]      = e0 * inv;
        if (lane + 32 < 49) sc[i * 49 + lane + 32] = e1 * inv;
    }
    __syncthreads();

    // out = P @ V
    for (int e = tid; e < 49 * 32; e += 256) {
        int i = e >> 5, d = e & 31;
        float accv = 0.f;
#pragma unroll 7
        for (int j = 0; j < 49; j++)
            accv = fmaf(sc[i * 49 + j], vs[j * 32 + d], accv);
        outp[((size_t)win * 49 + i) * CDIM + head * 32 + d] = accv;
    }
}

// ---------------- launch ----------------
extern "C" void kernel_launch(void* const* d_in, const int* in_sizes, int n_in,
                              void* d_out, int out_size) {
    const float* x      = (const float*)d_in[0];
    const float* n1g    = (const float*)d_in[1];
    const float* n1b    = (const float*)d_in[2];
    const float* qkv_w  = (const float*)d_in[3];
    const float* qkv_b  = (const float*)d_in[4];
    const float* rpb    = (const float*)d_in[5];
    const float* proj_w = (const float*)d_in[6];
    const float* proj_b = (const float*)d_in[7];
    const float* n2g    = (const float*)d_in[8];
    const float* n2b    = (const float*)d_in[9];
    const float* fc1_w  = (const float*)d_in[10];
    const float* fc1_b  = (const float*)d_in[11];
    const float* fc2_w  = (const float*)d_in[12];
    const float* fc2_b  = (const float*)d_in[13];
    float* out = (float*)d_out;

    float *p_xw, *p_qkv, *p_attn, *p_y, *p_h;
    cudaGetSymbolAddress((void**)&p_xw,   g_xw);
    cudaGetSymbolAddress((void**)&p_qkv,  g_qkv);
    cudaGetSymbolAddress((void**)&p_attn, g_attn);
    cudaGetSymbolAddress((void**)&p_y,    g_y);
    cudaGetSymbolAddress((void**)&p_h,    g_h);

    // 1. LN1 + shift + window partition
    ln_kernel<true><<<M_ROWS / 8, 256>>>(x, n1g, n1b, p_xw);
    // 2. QKV projection
    gemm_kernel<0><<<dim3(QKV3 / 64, M_ROWS / 128), 256>>>(p_xw, qkv_w, qkv_b, p_qkv, nullptr, CDIM, QKV3);
    // 3. windowed attention (bias + shift mask + softmax)
    attn_kernel<<<2048 * 6, 256>>>(p_qkv, rpb, p_attn);
    // 4. proj + window reverse + un-shift + residual  -> d_out holds x1
    gemm_kernel<1><<<dim3(CDIM / 64, M_ROWS / 128), 256>>>(p_attn, proj_w, proj_b, out, x, CDIM, CDIM);
    // 5. LN2
    ln_kernel<false><<<M_ROWS / 8, 256>>>(out, n2g, n2b, p_y);
    // 6. FC1 + GELU
    gemm_kernel<2><<<dim3(HIDDEN / 64, M_ROWS / 128), 256>>>(p_y, fc1_w, fc1_b, p_h, nullptr, CDIM, HIDDEN);
    // 7. FC2 + residual add into d_out
    gemm_kernel<3><<<dim3(CDIM / 64, M_ROWS / 128), 256>>>(p_h, fc2_w, fc2_b, out, fc2_b ? fc2_b : nullptr, HIDDEN, CDIM);
}

// round 3
// speedup vs baseline: 1.5275x; 1.5275x over previous
#include <cuda_runtime.h>
#include <math.h>

#define M_ROWS 100352   // 32 * 3136 = 2048 windows * 49
#define CDIM   192
#define HIDDEN 768
#define QKV3   576

// ---------------- scratch (no allocs allowed) ----------------
__device__ float g_xw  [(size_t)M_ROWS * CDIM];
__device__ float g_qkv [(size_t)M_ROWS * QKV3];
__device__ float g_attn[(size_t)M_ROWS * CDIM];
__device__ float g_y   [(size_t)M_ROWS * CDIM];
__device__ float g_h   [(size_t)M_ROWS * HIDDEN];

// window-layout row -> token index (handles cyclic shift by +3 on both axes)
__device__ __forceinline__ size_t win_row_to_token(int r) {
    int win = r / 49;
    int n   = r - win * 49;
    int b   = win >> 6;
    int wi  = win & 63;
    int ri  = n / 7;
    int ci  = n - ri * 7;
    int hs = (wi >> 3) * 7 + ri + 3; if (hs >= 56) hs -= 56;
    int ws = (wi & 7)  * 7 + ci + 3; if (ws >= 56) ws -= 56;
    return (size_t)b * 3136 + (size_t)hs * 56 + ws;
}

__device__ __forceinline__ unsigned f2tf32(float v) {
    unsigned r;
    asm("cvt.rna.tf32.f32 %0, %1;" : "=r"(r) : "f"(v));
    return r;
}

__device__ __forceinline__ void mma_tf32(float c[4], const unsigned a[4], const unsigned b[2]) {
    asm volatile(
        "mma.sync.aligned.m16n8k8.row.col.f32.tf32.tf32.f32 "
        "{%0,%1,%2,%3}, {%4,%5,%6,%7}, {%8,%9}, {%0,%1,%2,%3};"
        : "+f"(c[0]), "+f"(c[1]), "+f"(c[2]), "+f"(c[3])
        : "r"(a[0]), "r"(a[1]), "r"(a[2]), "r"(a[3]), "r"(b[0]), "r"(b[1]));
}

// ---------------- LayerNorm (1 warp per row) ----------------
template<bool GATHER>
__global__ __launch_bounds__(256)
void ln_kernel(const float* __restrict__ in, const float* __restrict__ gamma,
               const float* __restrict__ beta, float* __restrict__ out) {
    int row  = blockIdx.x * 8 + (threadIdx.x >> 5);
    int lane = threadIdx.x & 31;
    size_t t = GATHER ? win_row_to_token(row) : (size_t)row;
    const float* p = in + t * CDIM;
    float v[6];
    float s = 0.f, ss = 0.f;
#pragma unroll
    for (int i = 0; i < 6; i++) {
        v[i] = p[lane + 32 * i];
        s  += v[i];
        ss += v[i] * v[i];
    }
#pragma unroll
    for (int o = 16; o; o >>= 1) {
        s  += __shfl_xor_sync(0xffffffffu, s, o);
        ss += __shfl_xor_sync(0xffffffffu, ss, o);
    }
    float mu   = s * (1.f / CDIM);
    float var  = ss * (1.f / CDIM) - mu * mu;
    float rinv = rsqrtf(var + 1e-5f);
    float* q = out + (size_t)row * CDIM;
#pragma unroll
    for (int i = 0; i < 6; i++) {
        int c = lane + 32 * i;
        q[c] = (v[i] - mu) * rinv * gamma[c] + beta[c];
    }
}

// ---------------- tf32 tensor-core GEMM, fused epilogues ----------------
// MODE 0: C = A@B + bias                              (qkv)
// MODE 1: d_out[token] = x[token] + A@B + bias        (proj + window-reverse + residual)
// MODE 2: C = gelu(A@B + bias)                        (fc1)
// MODE 3: C += A@B + bias                             (fc2 + residual into d_out)
template<int MODE>
__global__ __launch_bounds__(256)
void gemm_tc(const float* __restrict__ A, const float* __restrict__ Bw,
             const float* __restrict__ bias, float* __restrict__ C,
             const float* __restrict__ extra, int K, int N) {
    __shared__ unsigned As[32][132];   // [k][m], pad -> conflict-free frag loads
    __shared__ unsigned Bs[32][68];    // [k][n], pad -> conflict-free frag loads

    const int tid  = threadIdx.x;
    const int warp = tid >> 5;
    const int lane = tid & 31;
    const int row0 = blockIdx.y * 128;
    const int col0 = blockIdx.x * 64;
    const int wm = (warp & 3) * 32;    // 4 warps along M
    const int wn = (warp >> 2) * 32;   // 2 warps along N
    const int g  = lane >> 2;          // 0..7
    const int tq = lane & 3;           // 0..3

    float acc[2][4][4];
#pragma unroll
    for (int mi = 0; mi < 2; mi++)
#pragma unroll
        for (int ni = 0; ni < 4; ni++)
#pragma unroll
            for (int j = 0; j < 4; j++) acc[mi][ni][j] = 0.f;

    const int nk = K >> 5;
    float4 pa[4], pb[2];

    // prefetch k-block 0
#pragma unroll
    for (int i = 0; i < 4; i++) {
        int idx = tid + i * 256;            // 0..1023
        int r = idx >> 3, kc = (idx & 7) * 4;
        pa[i] = *(const float4*)(A + (size_t)(row0 + r) * K + kc);
    }
#pragma unroll
    for (int i = 0; i < 2; i++) {
        int idx = tid + i * 256;            // 0..511
        int r = idx >> 4, nc = (idx & 15) * 4;
        pb[i] = *(const float4*)(Bw + (size_t)r * N + col0 + nc);
    }

    for (int kb = 0; kb < nk; kb++) {
        // store prefetched tile (tf32-converted)
#pragma unroll
        for (int i = 0; i < 4; i++) {
            int idx = tid + i * 256;
            int r = idx >> 3, kc = (idx & 7) * 4;
            As[kc + 0][r] = f2tf32(pa[i].x);
            As[kc + 1][r] = f2tf32(pa[i].y);
            As[kc + 2][r] = f2tf32(pa[i].z);
            As[kc + 3][r] = f2tf32(pa[i].w);
        }
#pragma unroll
        for (int i = 0; i < 2; i++) {
            int idx = tid + i * 256;
            int r = idx >> 4, nc = (idx & 15) * 4;
            Bs[r][nc + 0] = f2tf32(pb[i].x);
            Bs[r][nc + 1] = f2tf32(pb[i].y);
            Bs[r][nc + 2] = f2tf32(pb[i].z);
            Bs[r][nc + 3] = f2tf32(pb[i].w);
        }
        __syncthreads();

        // prefetch next k-block
        if (kb + 1 < nk) {
            int k0 = (kb + 1) * 32;
#pragma unroll
            for (int i = 0; i < 4; i++) {
                int idx = tid + i * 256;
                int r = idx >> 3, kc = (idx & 7) * 4;
                pa[i] = *(const float4*)(A + (size_t)(row0 + r) * K + k0 + kc);
            }
#pragma unroll
            for (int i = 0; i < 2; i++) {
                int idx = tid + i * 256;
                int r = idx >> 4, nc = (idx & 15) * 4;
                pb[i] = *(const float4*)(Bw + (size_t)(k0 + r) * N + col0 + nc);
            }
        }

        // compute: 4 k-steps of 8
#pragma unroll
        for (int ks = 0; ks < 4; ks++) {
            int kk = ks * 8;
            unsigned af[2][4], bf[4][2];
#pragma unroll
            for (int mi = 0; mi < 2; mi++) {
                af[mi][0] = As[kk + tq    ][wm + mi * 16 + g];
                af[mi][1] = As[kk + tq    ][wm + mi * 16 + g + 8];
                af[mi][2] = As[kk + tq + 4][wm + mi * 16 + g];
                af[mi][3] = As[kk + tq + 4][wm + mi * 16 + g + 8];
            }
#pragma unroll
            for (int ni = 0; ni < 4; ni++) {
                bf[ni][0] = Bs[kk + tq    ][wn + ni * 8 + g];
                bf[ni][1] = Bs[kk + tq + 4][wn + ni * 8 + g];
            }
#pragma unroll
            for (int mi = 0; mi < 2; mi++)
#pragma unroll
                for (int ni = 0; ni < 4; ni++)
                    mma_tf32(acc[mi][ni], af[mi], bf[ni]);
        }
        __syncthreads();
    }

    // epilogue: per fragment, rows (g, g+8), cols (tq*2, tq*2+1)
#pragma unroll
    for (int ni = 0; ni < 4; ni++) {
        int c = col0 + wn + ni * 8 + tq * 2;
        float bx = bias[c], by = bias[c + 1];
#pragma unroll
        for (int mi = 0; mi < 2; mi++) {
#pragma unroll
            for (int h = 0; h < 2; h++) {
                int r = row0 + wm + mi * 16 + g + h * 8;
                float ox = acc[mi][ni][h * 2 + 0] + bx;
                float oy = acc[mi][ni][h * 2 + 1] + by;
                if (MODE == 0) {
                    float2 o = {ox, oy};
                    *(float2*)(C + (size_t)r * N + c) = o;
                } else if (MODE == 1) {
                    size_t t = win_row_to_token(r);
                    float2 xv = *(const float2*)(extra + t * CDIM + c);
                    float2 o = {ox + xv.x, oy + xv.y};
                    *(float2*)(C + t * CDIM + c) = o;
                } else if (MODE == 2) {
                    float2 o;
                    o.x = 0.5f * ox * (1.f + erff(ox * 0.70710678118654752f));
                    o.y = 0.5f * oy * (1.f + erff(oy * 0.70710678118654752f));
                    *(float2*)(C + (size_t)r * N + c) = o;
                } else {
                    float2 cv = *(const float2*)(C + (size_t)r * N + c);
                    float2 o = {ox + cv.x, oy + cv.y};
                    *(float2*)(C + (size_t)r * N + c) = o;
                }
            }
        }
    }
}

// ---------------- windowed attention: 1 block per (window, head) ----------------
__global__ __launch_bounds__(256)
void attn_kernel(const float* __restrict__ qkv, const float* __restrict__ rpb,
                 float* __restrict__ outp) {
    int blk  = blockIdx.x;
    int win  = blk / 6;
    int head = blk % 6;

    __shared__ float qs[49 * 32];
    __shared__ float ksT[32 * 49];
    __shared__ float vs[49 * 32];
    __shared__ float sc[49 * 49];

    int tid = threadIdx.x;
    const float* base = qkv + (size_t)win * 49 * QKV3;

    for (int e = tid; e < 49 * 32; e += 256) {
        int n = e >> 5, d = e & 31;
        qs[e]            = base[n * QKV3 + head * 32 + d] * 0.17677669529663687f;
        ksT[d * 49 + n]  = base[n * QKV3 + 192 + head * 32 + d];
        vs[e]            = base[n * QKV3 + 384 + head * 32 + d];
    }
    __syncthreads();

    int wi = win & 63;
    int wy = wi >> 3, wx = wi & 7;

    for (int e = tid; e < 49 * 49; e += 256) {
        int i = e / 49, j = e - i * 49;
        const float* qi = qs + i * 32;
        float accv = 0.f;
#pragma unroll
        for (int d = 0; d < 32; d++)
            accv = fmaf(qi[d], ksT[d * 49 + j], accv);

        int yi = i / 7, xi = i - yi * 7;
        int yj = j / 7, xj = j - yj * 7;
        int idx = (yi - yj + 6) * 13 + (xi - xj + 6);
        accv += rpb[idx * 6 + head];

        int ri = wy * 7 + yi, ci = wx * 7 + xi;
        int rj = wy * 7 + yj, cj = wx * 7 + xj;
        int gi = (ri < 49 ? 0 : (ri < 53 ? 1 : 2)) * 3 + (ci < 49 ? 0 : (ci < 53 ? 1 : 2));
        int gj = (rj < 49 ? 0 : (rj < 53 ? 1 : 2)) * 3 + (cj < 49 ? 0 : (cj < 53 ? 1 : 2));
        if (gi != gj) accv -= 100.f;
        sc[e] = accv;
    }
    __syncthreads();

    int warp = tid >> 5, lane = tid & 31;
    for (int i = warp; i < 49; i += 8) {
        float v0 = (lane < 49)      ? sc[i * 49 + lane]      : -1e30f;
        float v1 = (lane + 32 < 49) ? sc[i * 49 + lane + 32] : -1e30f;
        float m = fmaxf(v0, v1);
#pragma unroll
        for (int o = 16; o; o >>= 1) m = fmaxf(m, __shfl_xor_sync(0xffffffffu, m, o));
        float e0 = (lane < 49)      ? __expf(v0 - m) : 0.f;
        float e1 = (lane + 32 < 49) ? __expf(v1 - m) : 0.f;
        float s = e0 + e1;
#pragma unroll
        for (int o = 16; o; o >>= 1) s += __shfl_xor_sync(0xffffffffu, s, o);
        float inv = 1.f / s;
        if (lane < 49)      sc[i * 49 + lane]      = e0 * inv;
        if (lane + 32 < 49) sc[i * 49 + lane + 32] = e1 * inv;
    }
    __syncthreads();

    for (int e = tid; e < 49 * 32; e += 256) {
        int i = e >> 5, d = e & 31;
        float accv = 0.f;
#pragma unroll 7
        for (int j = 0; j < 49; j++)
            accv = fmaf(sc[i * 49 + j], vs[j * 32 + d], accv);
        outp[((size_t)win * 49 + i) * CDIM + head * 32 + d] = accv;
    }
}

// ---------------- launch ----------------
extern "C" void kernel_launch(void* const* d_in, const int* in_sizes, int n_in,
                              void* d_out, int out_size) {
    const float* x      = (const float*)d_in[0];
    const float* n1g    = (const float*)d_in[1];
    const float* n1b    = (const float*)d_in[2];
    const float* qkv_w  = (const float*)d_in[3];
    const float* qkv_b  = (const float*)d_in[4];
    const float* rpb    = (const float*)d_in[5];
    const float* proj_w = (const float*)d_in[6];
    const float* proj_b = (const float*)d_in[7];
    const float* n2g    = (const float*)d_in[8];
    const float* n2b    = (const float*)d_in[9];
    const float* fc1_w  = (const float*)d_in[10];
    const float* fc1_b  = (const float*)d_in[11];
    const float* fc2_w  = (const float*)d_in[12];
    const float* fc2_b  = (const float*)d_in[13];
    float* out = (float*)d_out;

    float *p_xw, *p_qkv, *p_attn, *p_y, *p_h;
    cudaGetSymbolAddress((void**)&p_xw,   g_xw);
    cudaGetSymbolAddress((void**)&p_qkv,  g_qkv);
    cudaGetSymbolAddress((void**)&p_attn, g_attn);
    cudaGetSymbolAddress((void**)&p_y,    g_y);
    cudaGetSymbolAddress((void**)&p_h,    g_h);

    // 1. LN1 + shift + window partition
    ln_kernel<true><<<M_ROWS / 8, 256>>>(x, n1g, n1b, p_xw);
    // 2. QKV projection
    gemm_tc<0><<<dim3(QKV3 / 64, M_ROWS / 128), 256>>>(p_xw, qkv_w, qkv_b, p_qkv, nullptr, CDIM, QKV3);
    // 3. windowed attention
    attn_kernel<<<2048 * 6, 256>>>(p_qkv, rpb, p_attn);
    // 4. proj + window reverse + un-shift + residual -> d_out holds x1
    gemm_tc<1><<<dim3(CDIM / 64, M_ROWS / 128), 256>>>(p_attn, proj_w, proj_b, out, x, CDIM, CDIM);
    // 5. LN2
    ln_kernel<false><<<M_ROWS / 8, 256>>>(out, n2g, n2b, p_y);
    // 6. FC1 + GELU
    gemm_tc<2><<<dim3(HIDDEN / 64, M_ROWS / 128), 256>>>(p_y, fc1_w, fc1_b, p_h, nullptr, CDIM, HIDDEN);
    // 7. FC2 + residual add into d_out
    gemm_tc<3><<<dim3(CDIM / 64, M_ROWS / 128), 256>>>(p_h, fc2_w, fc2_b, out, nullptr, HIDDEN, CDIM);
}

// round 5
// speedup vs baseline: 2.0675x; 1.3536x over previous
#include <cuda_runtime.h>
#include <math.h>
#include <stdint.h>

#define M_ROWS 100352   // 32 * 3136 = 2048 windows * 49
#define CDIM   192
#define HIDDEN 768
#define QKV3   576

// GEMM tiling: block 128x64, 4 warps of 64x32, 3-stage cp.async pipeline
#define TM 128
#define TN 64
#define NSTAGE 3
#define A_PITCH 36                    // floats per A row (pad 4) -> frag bank = 4g+tq
#define B_PITCH 72                    // floats per B row (pad 8) -> frag bank = 8tq+g
#define ASZ (TM * A_PITCH)            // 4608 floats / stage
#define BSZ (32 * B_PITCH)            // 2304 floats / stage
#define SMEM_SZ ((NSTAGE * (ASZ + BSZ)) * 4)   // 82944 bytes

// ---------------- scratch (no allocs allowed) ----------------
__device__ float g_xw  [(size_t)M_ROWS * CDIM];
__device__ float g_qkv [(size_t)M_ROWS * QKV3];
__device__ float g_attn[(size_t)M_ROWS * CDIM];
__device__ float g_y   [(size_t)M_ROWS * CDIM];
__device__ float g_h   [(size_t)M_ROWS * HIDDEN];

// ---------------- helpers ----------------
__device__ __forceinline__ uint32_t smem_u32(const void* p) {
    uint32_t a;
    asm("{ .reg .u64 t; cvta.to.shared.u64 t, %1; cvt.u32.u64 %0, t; }" : "=r"(a) : "l"(p));
    return a;
}
__device__ __forceinline__ void cpa16(uint32_t dst, const void* src) {
    asm volatile("cp.async.cg.shared.global [%0], [%1], 16;" :: "r"(dst), "l"(src));
}
#define CP_COMMIT() asm volatile("cp.async.commit_group;" ::: "memory")
#define CP_WAIT1()  asm volatile("cp.async.wait_group 1;" ::: "memory")

__device__ __forceinline__ void mma_tf32(float c[4], const unsigned a[4], const unsigned b[2]) {
    asm volatile(
        "mma.sync.aligned.m16n8k8.row.col.f32.tf32.tf32.f32 "
        "{%0,%1,%2,%3}, {%4,%5,%6,%7}, {%8,%9}, {%0,%1,%2,%3};"
        : "+f"(c[0]), "+f"(c[1]), "+f"(c[2]), "+f"(c[3])
        : "r"(a[0]), "r"(a[1]), "r"(a[2]), "r"(a[3]), "r"(b[0]), "r"(b[1]));
}

// window-layout row -> token index (cyclic shift by +3 both axes)
__device__ __forceinline__ size_t win_row_to_token(int r) {
    int win = r / 49;
    int n   = r - win * 49;
    int b   = win >> 6;
    int wi  = win & 63;
    int ri  = n / 7;
    int ci  = n - ri * 7;
    int hs = (wi >> 3) * 7 + ri + 3; if (hs >= 56) hs -= 56;
    int ws = (wi & 7)  * 7 + ci + 3; if (ws >= 56) ws -= 56;
    return (size_t)b * 3136 + (size_t)hs * 56 + ws;
}

// ---------------- LayerNorm (1 warp per row) ----------------
template<bool GATHER>
__global__ __launch_bounds__(256)
void ln_kernel(const float* __restrict__ in, const float* __restrict__ gamma,
               const float* __restrict__ beta, float* __restrict__ out) {
    int row  = blockIdx.x * 8 + (threadIdx.x >> 5);
    int lane = threadIdx.x & 31;
    size_t t = GATHER ? win_row_to_token(row) : (size_t)row;
    const float* p = in + t * CDIM;
    float v[6];
    float s = 0.f, ss = 0.f;
#pragma unroll
    for (int i = 0; i < 6; i++) {
        v[i] = p[lane + 32 * i];
        s  += v[i];
        ss += v[i] * v[i];
    }
#pragma unroll
    for (int o = 16; o; o >>= 1) {
        s  += __shfl_xor_sync(0xffffffffu, s, o);
        ss += __shfl_xor_sync(0xffffffffu, ss, o);
    }
    float mu   = s * (1.f / CDIM);
    float var  = ss * (1.f / CDIM) - mu * mu;
    float rinv = rsqrtf(var + 1e-5f);
    float* q = out + (size_t)row * CDIM;
#pragma unroll
    for (int i = 0; i < 6; i++) {
        int c = lane + 32 * i;
        q[c] = (v[i] - mu) * rinv * gamma[c] + beta[c];
    }
}

// ---------------- tf32 mma.sync GEMM, cp.async 3-stage, fused epilogues ----------------
// MODE 0: C = A@B + bias                       (qkv)
// MODE 1: d_out[token] = x[token] + A@B + bias (proj + window-reverse + residual)
// MODE 2: C = gelu(A@B + bias)                 (fc1)
// MODE 3: C += A@B + bias                      (fc2 + residual into d_out)
template<int MODE>
__global__ __launch_bounds__(128)
void gemm_tc(const float* __restrict__ A, const float* __restrict__ Bw,
             const float* __restrict__ bias, float* __restrict__ C,
             const float* __restrict__ extra, int K, int N) {
    extern __shared__ __align__(16) float smem[];
    float* As_all = smem;
    float* Bs_all = smem + NSTAGE * ASZ;
    const uint32_t as_u = smem_u32(As_all);
    const uint32_t bs_u = smem_u32(Bs_all);

    const int tid  = threadIdx.x;
    const int warp = tid >> 5;
    const int lane = tid & 31;
    const int row0 = blockIdx.y * TM;
    const int col0 = blockIdx.x * TN;
    const int wm = (warp & 1) * 64;
    const int wn = (warp >> 1) * 32;
    const int g  = lane >> 2;
    const int tq = lane & 3;
    const int nk = K >> 5;

    // cp.async issue of k-block kb into stage s
    auto issue = [&](int kb, int s) {
        const float* Abase = A + (size_t)row0 * K + kb * 32;
        uint32_t ad = as_u + (uint32_t)s * ASZ * 4;
#pragma unroll
        for (int u = 0; u < 8; u++) {
            int idx = tid + u * 128;
            int m = idx >> 3, c = idx & 7;
            cpa16(ad + (uint32_t)(m * A_PITCH + c * 4) * 4, Abase + (size_t)m * K + c * 4);
        }
        const float* Bbase = Bw + (size_t)(kb * 32) * N + col0;
        uint32_t bd = bs_u + (uint32_t)s * BSZ * 4;
#pragma unroll
        for (int u = 0; u < 4; u++) {
            int idx = tid + u * 128;
            int k = idx >> 4, c = idx & 15;
            cpa16(bd + (uint32_t)(k * B_PITCH + c * 4) * 4, Bbase + (size_t)k * N + c * 4);
        }
    };

    float acc[4][4][4];
#pragma unroll
    for (int mi = 0; mi < 4; mi++)
#pragma unroll
        for (int ni = 0; ni < 4; ni++)
#pragma unroll
            for (int j = 0; j < 4; j++) acc[mi][ni][j] = 0.f;

    issue(0, 0); CP_COMMIT();
    issue(1, 1); CP_COMMIT();

    for (int kb = 0; kb < nk; kb++) {
        CP_WAIT1();
        __syncthreads();
        int s = kb % NSTAGE;
        if (kb + 2 < nk) issue(kb + 2, (kb + 2) % NSTAGE);
        CP_COMMIT();

        const float* a = As_all + s * ASZ;
        const float* b = Bs_all + s * BSZ;
#pragma unroll
        for (int ks = 0; ks < 4; ks++) {
            int kk = ks * 8;
            unsigned af[4][4], bf[4][2];
#pragma unroll
            for (int mi = 0; mi < 4; mi++) {
                int m0 = wm + mi * 16;
                af[mi][0] = __float_as_uint(a[(m0 + g)     * A_PITCH + kk + tq]);
                af[mi][1] = __float_as_uint(a[(m0 + g + 8) * A_PITCH + kk + tq]);
                af[mi][2] = __float_as_uint(a[(m0 + g)     * A_PITCH + kk + tq + 4]);
                af[mi][3] = __float_as_uint(a[(m0 + g + 8) * A_PITCH + kk + tq + 4]);
            }
#pragma unroll
            for (int ni = 0; ni < 4; ni++) {
                int n0 = wn + ni * 8;
                bf[ni][0] = __float_as_uint(b[(kk + tq)     * B_PITCH + n0 + g]);
                bf[ni][1] = __float_as_uint(b[(kk + tq + 4) * B_PITCH + n0 + g]);
            }
#pragma unroll
            for (int mi = 0; mi < 4; mi++)
#pragma unroll
                for (int ni = 0; ni < 4; ni++)
                    mma_tf32(acc[mi][ni], af[mi], bf[ni]);
        }
        __syncthreads();
    }

    // epilogue: thread (g,tq) holds rows (g, g+8), cols (2tq, 2tq+1) per tile
#pragma unroll
    for (int mi = 0; mi < 4; mi++) {
#pragma unroll
        for (int h = 0; h < 2; h++) {
            int r = row0 + wm + mi * 16 + g + h * 8;
            float* dst;
            const float* xrow = nullptr;
            if (MODE == 1) {
                size_t t = win_row_to_token(r);
                dst = C + t * CDIM;
                xrow = extra + t * CDIM;
            } else {
                dst = C + (size_t)r * N;
            }
#pragma unroll
            for (int ni = 0; ni < 4; ni++) {
                int c = col0 + wn + ni * 8 + tq * 2;
                float ox = acc[mi][ni][h * 2 + 0] + bias[c];
                float oy = acc[mi][ni][h * 2 + 1] + bias[c + 1];
                if (MODE == 0) {
                    float2 o = {ox, oy};
                    *(float2*)(dst + c) = o;
                } else if (MODE == 1) {
                    float2 xv = *(const float2*)(xrow + c);
                    float2 o = {ox + xv.x, oy + xv.y};
                    *(float2*)(dst + c) = o;
                } else if (MODE == 2) {
                    float2 o;
                    o.x = 0.5f * ox * (1.f + erff(ox * 0.70710678118654752f));
                    o.y = 0.5f * oy * (1.f + erff(oy * 0.70710678118654752f));
                    *(float2*)(dst + c) = o;
                } else {
                    float2 cv = *(const float2*)(dst + c);
                    float2 o = {ox + cv.x, oy + cv.y};
                    *(float2*)(dst + c) = o;
                }
            }
        }
    }
}

// ---------------- windowed attention: 1 block per (window, head) ----------------
__global__ __launch_bounds__(256)
void attn_kernel(const float* __restrict__ qkv, const float* __restrict__ rpb,
                 float* __restrict__ outp) {
    int blk  = blockIdx.x;
    int win  = blk / 6;
    int head = blk % 6;

    __shared__ float qs[49 * 32];
    __shared__ float ksT[32 * 49];
    __shared__ float vs[49 * 32];
    __shared__ float sc[49 * 49];

    int tid = threadIdx.x;
    const float* base = qkv + (size_t)win * 49 * QKV3;

    for (int e = tid; e < 49 * 32; e += 256) {
        int n = e >> 5, d = e & 31;
        qs[e]            = base[n * QKV3 + head * 32 + d] * 0.17677669529663687f;
        ksT[d * 49 + n]  = base[n * QKV3 + 192 + head * 32 + d];
        vs[e]            = base[n * QKV3 + 384 + head * 32 + d];
    }
    __syncthreads();

    int wi = win & 63;
    int wy = wi >> 3, wx = wi & 7;

    for (int e = tid; e < 49 * 49; e += 256) {
        int i = e / 49, j = e - i * 49;
        const float* qi = qs + i * 32;
        float accv = 0.f;
#pragma unroll
        for (int d = 0; d < 32; d++)
            accv = fmaf(qi[d], ksT[d * 49 + j], accv);

        int yi = i / 7, xi = i - yi * 7;
        int yj = j / 7, xj = j - yj * 7;
        int idx = (yi - yj + 6) * 13 + (xi - xj + 6);
        accv += rpb[idx * 6 + head];

        int ri = wy * 7 + yi, ci = wx * 7 + xi;
        int rj = wy * 7 + yj, cj = wx * 7 + xj;
        int gi = (ri < 49 ? 0 : (ri < 53 ? 1 : 2)) * 3 + (ci < 49 ? 0 : (ci < 53 ? 1 : 2));
        int gj = (rj < 49 ? 0 : (rj < 53 ? 1 : 2)) * 3 + (cj < 49 ? 0 : (cj < 53 ? 1 : 2));
        if (gi != gj) accv -= 100.f;
        sc[e] = accv;
    }
    __syncthreads();

    int warp = tid >> 5, lane = tid & 31;
    for (int i = warp; i < 49; i += 8) {
        float v0 = (lane < 49)      ? sc[i * 49 + lane]      : -1e30f;
        float v1 = (lane + 32 < 49) ? sc[i * 49 + lane + 32] : -1e30f;
        float m = fmaxf(v0, v1);
#pragma unroll
        for (int o = 16; o; o >>= 1) m = fmaxf(m, __shfl_xor_sync(0xffffffffu, m, o));
        float e0 = (lane < 49)      ? __expf(v0 - m) : 0.f;
        float e1 = (lane + 32 < 49) ? __expf(v1 - m) : 0.f;
        float s = e0 + e1;
#pragma unroll
        for (int o = 16; o; o >>= 1) s += __shfl_xor_sync(0xffffffffu, s, o);
        float inv = 1.f / s;
        if (lane < 49)      sc[i * 49 + lane]      = e0 * inv;
        if (lane + 32 < 49) sc[i * 49 + lane + 32] = e1 * inv;
    }
    __syncthreads();

    for (int e = tid; e < 49 * 32; e += 256) {
        int i = e >> 5, d = e & 31;
        float accv = 0.f;
#pragma unroll 7
        for (int j = 0; j < 49; j++)
            accv = fmaf(sc[i * 49 + j], vs[j * 32 + d], accv);
        outp[((size_t)win * 49 + i) * CDIM + head * 32 + d] = accv;
    }
}

// ---------------- launch ----------------
extern "C" void kernel_launch(void* const* d_in, const int* in_sizes, int n_in,
                              void* d_out, int out_size) {
    const float* x      = (const float*)d_in[0];
    const float* n1g    = (const float*)d_in[1];
    const float* n1b    = (const float*)d_in[2];
    const float* qkv_w  = (const float*)d_in[3];
    const float* qkv_b  = (const float*)d_in[4];
    const float* rpb    = (const float*)d_in[5];
    const float* proj_w = (const float*)d_in[6];
    const float* proj_b = (const float*)d_in[7];
    const float* n2g    = (const float*)d_in[8];
    const float* n2b    = (const float*)d_in[9];
    const float* fc1_w  = (const float*)d_in[10];
    const float* fc1_b  = (const float*)d_in[11];
    const float* fc2_w  = (const float*)d_in[12];
    const float* fc2_b  = (const float*)d_in[13];
    float* out = (float*)d_out;

    float *p_xw, *p_qkv, *p_attn, *p_y, *p_h;
    cudaGetSymbolAddress((void**)&p_xw,   g_xw);
    cudaGetSymbolAddress((void**)&p_qkv,  g_qkv);
    cudaGetSymbolAddress((void**)&p_attn, g_attn);
    cudaGetSymbolAddress((void**)&p_y,    g_y);
    cudaGetSymbolAddress((void**)&p_h,    g_h);

    cudaFuncSetAttribute(gemm_tc<0>, cudaFuncAttributeMaxDynamicSharedMemorySize, SMEM_SZ);
    cudaFuncSetAttribute(gemm_tc<1>, cudaFuncAttributeMaxDynamicSharedMemorySize, SMEM_SZ);
    cudaFuncSetAttribute(gemm_tc<2>, cudaFuncAttributeMaxDynamicSharedMemorySize, SMEM_SZ);
    cudaFuncSetAttribute(gemm_tc<3>, cudaFuncAttributeMaxDynamicSharedMemorySize, SMEM_SZ);

    const int MT = M_ROWS / TM;   // 784

    // 1. LN1 + shift + window partition
    ln_kernel<true><<<M_ROWS / 8, 256>>>(x, n1g, n1b, p_xw);
    // 2. QKV projection
    gemm_tc<0><<<dim3(QKV3 / TN, MT), 128, SMEM_SZ>>>(p_xw, qkv_w, qkv_b, p_qkv, nullptr, CDIM, QKV3);
    // 3. windowed attention
    attn_kernel<<<2048 * 6, 256>>>(p_qkv, rpb, p_attn);
    // 4. proj + window reverse + un-shift + residual -> d_out holds x1
    gemm_tc<1><<<dim3(CDIM / TN, MT), 128, SMEM_SZ>>>(p_attn, proj_w, proj_b, out, x, CDIM, CDIM);
    // 5. LN2
    ln_kernel<false><<<M_ROWS / 8, 256>>>(out, n2g, n2b, p_y);
    // 6. FC1 + GELU
    gemm_tc<2><<<dim3(HIDDEN / TN, MT), 128, SMEM_SZ>>>(p_y, fc1_w, fc1_b, p_h, nullptr, CDIM, HIDDEN);
    // 7. FC2 + residual add into d_out
    gemm_tc<3><<<dim3(CDIM / TN, MT), 128, SMEM_SZ>>>(p_h, fc2_w, fc2_b, out, nullptr, HIDDEN, CDIM);
}